// round 5
// baseline (speedup 1.0000x reference)
#include <cuda_runtime.h>
#include <math.h>
#include <stdint.h>

// Problem constants
#define BB     2
#define LL     1024
#define HH     768
#define NHEADS 12
#define NE     24
#define MM     3
#define NC     2
#define CWW    8
#define BLK    64
#define NCLS   97
#define KB     12              // H / BLOCK
#define QTOT   (HH*BLK)        // 49152
#define NS     (BB*NE*NE)      // 1152
#define NPAD   128
#define QSL    4               // q slices in logits kernel (3 k-blocks each)

// ---------------- device scratch (no runtime allocation allowed) ----------------
__device__ float g_eatt[BB*NE*NHEADS*LL];       // (b,e,h,l)  mean over mentions
__device__ float g_eemb[BB*NE*HH];              // logsumexp entity embedding
__device__ float g_ht[BB*NE*NE*LL];             // normalized relu attention product
__device__ float g_rs[(size_t)NS*HH];           // context vectors
__device__ float g_Ah[BB*NE*HH];                // e_emb @ Wh1^T + b_head
__device__ float g_At[BB*NE*HH];                // e_emb @ Wt1^T + b_tail
__device__ float g_zh[(size_t)NS*HH];
__device__ float g_zt[(size_t)NS*HH];
__device__ float g_WclsT[HH*NPAD];              // W_cls transposed, n-padded to 128
__device__ float g_Wc[(size_t)QTOT*NPAD];       // folded W_cls @ W_proj, layout [q][n]
__device__ float g_part[QSL*NS*NCLS];           // logits partial sums per q-slice

// ---------------- Kernel 1: entity gather / gate / coref / logsumexp ----------------
__global__ void k_entity(const float* __restrict__ seq, const float* __restrict__ att,
                         const int* __restrict__ mst, const int* __restrict__ cst)
{
    int be  = blockIdx.x;           // b*NE + e
    int b   = be / NE;
    int tid = threadIdx.x;

    __shared__ float s_att[LL];
    __shared__ float s_gate[NC*CWW];
    __shared__ float s_red[256];
    __shared__ int   s_p[MM];
    __shared__ int   s_c[NC];

    if (tid < MM) s_p[tid] = mst[be*MM + tid] + 1;      // OFFSET = 1
    if (tid >= 32 && tid < 32+NC) s_c[tid-32] = cst[be*NC + (tid-32)];
    __syncthreads();

    int p0 = s_p[0], p1 = s_p[1], p2 = s_p[2];
    const float* ab = att + (size_t)b*NHEADS*LL*LL;

    for (int h = 0; h < NHEADS; ++h) {
        const float* r0 = ab + ((size_t)h*LL + p0)*LL;
        const float* r1 = ab + ((size_t)h*LL + p1)*LL;
        const float* r2 = ab + ((size_t)h*LL + p2)*LL;
        float* eo = g_eatt + ((size_t)be*NHEADS + h)*LL;
        for (int l = tid; l < LL; l += 256) {
            float v = (r0[l] + r1[l] + r2[l]) * (1.0f/3.0f);
            eo[l] = v;
            if (h == 0) s_att[l] = v; else s_att[l] += v;
        }
    }
    __syncthreads();

    float lsum = 0.f;
    for (int l = tid; l < LL; l += 256) lsum += s_att[l];
    s_red[tid] = lsum;
    __syncthreads();
    for (int off = 128; off > 0; off >>= 1) {
        if (tid < off) s_red[tid] += s_red[tid+off];
        __syncthreads();
    }
    float inv = 1.0f / s_red[0];

    if (tid < NC*CWW) {
        int c = tid / CWW, w = tid % CWW;
        s_gate[tid] = s_att[s_c[c] + w] * inv;
    }
    __syncthreads();

    const float* sb = seq + (size_t)b*LL*HH;
    int c0 = s_c[0], c1 = s_c[1];
    for (int d = tid; d < HH; d += 256) {
        float v0 = sb[(size_t)p0*HH + d];
        float v1 = sb[(size_t)p1*HH + d];
        float v2 = sb[(size_t)p2*HH + d];
        float v3 = 0.f, v4 = 0.f;
        #pragma unroll
        for (int w = 0; w < CWW; ++w) {
            v3 += s_gate[w]       * sb[(size_t)(c0+w)*HH + d];
            v4 += s_gate[CWW+w]   * sb[(size_t)(c1+w)*HH + d];
        }
        float mx = fmaxf(fmaxf(fmaxf(v0,v1), fmaxf(v2,v3)), v4);
        float s  = expf(v0-mx)+expf(v1-mx)+expf(v2-mx)+expf(v3-mx)+expf(v4-mx);
        g_eemb[(size_t)be*HH + d] = mx + logf(s);
    }
}

// ---------------- Kernel 2: ht = norm(relu(e_att . e_att^T over heads)) ----------------
__global__ void k_ht()
{
    int bef = blockIdx.x;                   // b*NE*NE + e*NE + f
    int b = bef / (NE*NE);
    int ef = bef % (NE*NE);
    int e = ef / NE, f = ef % NE;
    const float* pe = g_eatt + (size_t)(b*NE+e)*NHEADS*LL;
    const float* pf = g_eatt + (size_t)(b*NE+f)*NHEADS*LL;
    int tid = threadIdx.x;
    __shared__ float s_red[256];

    float v[4];
    float lsum = 0.f;
    #pragma unroll
    for (int r = 0; r < 4; ++r) {
        int l = r*256 + tid;
        float acc = 0.f;
        #pragma unroll
        for (int h = 0; h < NHEADS; ++h)
            acc += pe[h*LL + l] * pf[h*LL + l];
        v[r] = fmaxf(acc, 0.f);
        lsum += v[r];
    }
    s_red[tid] = lsum;
    __syncthreads();
    for (int off = 128; off > 0; off >>= 1) {
        if (tid < off) s_red[tid] += s_red[tid+off];
        __syncthreads();
    }
    float invn = 1.0f / (s_red[0] + 1e-10f);
    float* out = g_ht + (size_t)bef*LL;
    #pragma unroll
    for (int r = 0; r < 4; ++r) out[r*256 + tid] = v[r] * invn;
}

// ---------------- Kernel 3: rs[b] = ht[b] (576x1024) @ seq[b] (1024x768) ----------------
__global__ void k_rs(const float* __restrict__ seq)
{
    const int BM=64, BN=64, BK=16;
    int bm = blockIdx.x, bn = blockIdx.y, b = blockIdx.z;
    const float* A  = g_ht + (size_t)b*NE*NE*LL;
    const float* Bm = seq  + (size_t)b*LL*HH;
    __shared__ float As[BK][BM];
    __shared__ float Bs[BK][BN];
    int tid = threadIdx.x;
    int tx = tid % 16, ty = tid / 16;
    int arow = tid / 4,  acol4 = (tid % 4) * 4;
    int brow = tid / 16, bcol4 = (tid % 16) * 4;
    float acc[4][4] = {};

    for (int k0 = 0; k0 < LL; k0 += BK) {
        float4 a4 = *(const float4*)(A  + (size_t)(bm*BM + arow)*LL + k0 + acol4);
        float4 b4 = *(const float4*)(Bm + (size_t)(k0 + brow)*HH + bn*BN + bcol4);
        As[acol4+0][arow] = a4.x; As[acol4+1][arow] = a4.y;
        As[acol4+2][arow] = a4.z; As[acol4+3][arow] = a4.w;
        *(float4*)&Bs[brow][bcol4] = b4;
        __syncthreads();
        #pragma unroll
        for (int kk = 0; kk < BK; ++kk) {
            float4 av = *(float4*)&As[kk][ty*4];
            float4 bv = *(float4*)&Bs[kk][tx*4];
            acc[0][0]+=av.x*bv.x; acc[0][1]+=av.x*bv.y; acc[0][2]+=av.x*bv.z; acc[0][3]+=av.x*bv.w;
            acc[1][0]+=av.y*bv.x; acc[1][1]+=av.y*bv.y; acc[1][2]+=av.y*bv.z; acc[1][3]+=av.y*bv.w;
            acc[2][0]+=av.z*bv.x; acc[2][1]+=av.z*bv.y; acc[2][2]+=av.z*bv.z; acc[2][3]+=av.z*bv.w;
            acc[3][0]+=av.w*bv.x; acc[3][1]+=av.w*bv.y; acc[3][2]+=av.w*bv.z; acc[3][3]+=av.w*bv.w;
        }
        __syncthreads();
    }
    #pragma unroll
    for (int i = 0; i < 4; ++i) {
        float4 o = make_float4(acc[i][0], acc[i][1], acc[i][2], acc[i][3]);
        *(float4*)(g_rs + (size_t)(b*NE*NE + bm*BM + ty*4 + i)*HH + bn*BN + tx*4) = o;
    }
}

// ---------------- Kernel 4a: Ah/At = e_emb @ W1^T + bias (hoisted hs/ts halves) ---------
__global__ void k_AhAt(const float* __restrict__ Wh, const float* __restrict__ bh,
                       const float* __restrict__ Wt, const float* __restrict__ bt)
{
    int be = blockIdx.x;
    int which = blockIdx.y;
    const float* W    = which ? Wt : Wh;
    const float* bias = which ? bt : bh;
    float* out = (which ? g_At : g_Ah) + (size_t)be*HH;
    __shared__ float s_e[HH];
    int tid = threadIdx.x;
    for (int d = tid; d < HH; d += 256) s_e[d] = g_eemb[(size_t)be*HH + d];
    __syncthreads();
    for (int d = tid; d < HH; d += 256) {
        const float4* wr = (const float4*)(W + (size_t)d*(2*HH));   // first H columns
        float acc = 0.f;
        #pragma unroll 4
        for (int j4 = 0; j4 < HH/4; ++j4) {
            float4 w = wr[j4];
            float4 e = *(const float4*)&s_e[j4*4];
            acc += w.x*e.x + w.y*e.y + w.z*e.z + w.w*e.w;
        }
        out[d] = acc + bias[d];
    }
}

// ---------------- Kernel 4b: [zh|zt] = tanh(rs @ W2^T + A) -----------------------------
__global__ void k_zhzt(const float* __restrict__ Wh, const float* __restrict__ Wt)
{
    const int BM=64, BN=64, BK=16;
    int bm = blockIdx.x, bn = blockIdx.y;
    bool isHead = (bn < HH/BN);
    const float* W = isHead ? Wh : Wt;
    int ncol0 = (isHead ? bn : bn - HH/BN) * BN;

    __shared__ float As[BK][BM];
    __shared__ float Bs[BK][BN];
    int tid = threadIdx.x;
    int tx = tid % 16, ty = tid / 16;
    int arow = tid / 4, acol4 = (tid % 4) * 4;
    float acc[4][4] = {};

    for (int k0 = 0; k0 < HH; k0 += BK) {
        float4 a4 = *(const float4*)(g_rs + (size_t)(bm*BM + arow)*HH + k0 + acol4);
        // B^T source: W[n][H + k]  (rows = out dim n, second-H columns)
        float4 b4 = *(const float4*)(W + (size_t)(ncol0 + arow)*(2*HH) + HH + k0 + acol4);
        As[acol4+0][arow] = a4.x; As[acol4+1][arow] = a4.y;
        As[acol4+2][arow] = a4.z; As[acol4+3][arow] = a4.w;
        Bs[acol4+0][arow] = b4.x; Bs[acol4+1][arow] = b4.y;
        Bs[acol4+2][arow] = b4.z; Bs[acol4+3][arow] = b4.w;
        __syncthreads();
        #pragma unroll
        for (int kk = 0; kk < BK; ++kk) {
            float4 av = *(float4*)&As[kk][ty*4];
            float4 bv = *(float4*)&Bs[kk][tx*4];
            acc[0][0]+=av.x*bv.x; acc[0][1]+=av.x*bv.y; acc[0][2]+=av.x*bv.z; acc[0][3]+=av.x*bv.w;
            acc[1][0]+=av.y*bv.x; acc[1][1]+=av.y*bv.y; acc[1][2]+=av.y*bv.z; acc[1][3]+=av.y*bv.w;
            acc[2][0]+=av.z*bv.x; acc[2][1]+=av.z*bv.y; acc[2][2]+=av.z*bv.z; acc[2][3]+=av.z*bv.w;
            acc[3][0]+=av.w*bv.x; acc[3][1]+=av.w*bv.y; acc[3][2]+=av.w*bv.z; acc[3][3]+=av.w*bv.w;
        }
        __syncthreads();
    }
    float* Z = isHead ? g_zh : g_zt;
    #pragma unroll
    for (int i = 0; i < 4; ++i) {
        int s  = bm*BM + ty*4 + i;
        int b  = s / (NE*NE);
        int ef = s % (NE*NE);
        int e  = ef / NE, f = ef % NE;
        const float* Avec = isHead ? (g_Ah + (size_t)(b*NE+e)*HH)
                                   : (g_At + (size_t)(b*NE+f)*HH);
        #pragma unroll
        for (int j = 0; j < 4; ++j) {
            int col = ncol0 + tx*4 + j;
            Z[(size_t)s*HH + col] = tanhf(acc[i][j] + Avec[col]);
        }
    }
}

// ---------------- Kernel 5a: transpose W_cls -> [d][n] padded to 128 -------------------
__global__ void k_wclsT(const float* __restrict__ Wcls)
{
    int idx = blockIdx.x*256 + threadIdx.x;
    if (idx >= HH*NPAD) return;
    int d = idx / NPAD, n = idx % NPAD;
    g_WclsT[idx] = (n < NCLS) ? Wcls[(size_t)n*HH + d] : 0.f;
}

// ---------------- Kernel 5b: Wc[q][n] = sum_d W_proj[d][q] * W_cls[n][d] ---------------
__global__ void k_wc(const float* __restrict__ Wproj)
{
    const int QT = 64, DB = 16;
    int q0 = blockIdx.x * QT;
    int tid = threadIdx.x, tx = tid % 32, ty = tid / 32;
    __shared__ float Wp_s[DB][QT];
    __shared__ float Wt_s[DB][NPAD];
    float acc[8][4] = {};

    int pr = tid / 16, pc4 = (tid % 16) * 4;    // Wp tile load map
    int cr = tid / 32, cc4 = (tid % 32) * 4;    // WclsT tile load map

    for (int d0 = 0; d0 < HH; d0 += DB) {
        *(float4*)&Wp_s[pr][pc4]   = *(const float4*)(Wproj + (size_t)(d0+pr)*QTOT + q0 + pc4);
        *(float4*)&Wt_s[cr][cc4]   = *(const float4*)(g_WclsT + (size_t)(d0+cr)*NPAD + cc4);
        *(float4*)&Wt_s[cr+8][cc4] = *(const float4*)(g_WclsT + (size_t)(d0+cr+8)*NPAD + cc4);
        __syncthreads();
        #pragma unroll
        for (int dd = 0; dd < DB; ++dd) {
            float4 wq0 = *(float4*)&Wp_s[dd][ty*8];
            float4 wq1 = *(float4*)&Wp_s[dd][ty*8+4];
            float4 wn  = *(float4*)&Wt_s[dd][tx*4];
            float wq[8] = {wq0.x,wq0.y,wq0.z,wq0.w,wq1.x,wq1.y,wq1.z,wq1.w};
            #pragma unroll
            for (int r = 0; r < 8; ++r) {
                acc[r][0] += wq[r]*wn.x;
                acc[r][1] += wq[r]*wn.y;
                acc[r][2] += wq[r]*wn.z;
                acc[r][3] += wq[r]*wn.w;
            }
        }
        __syncthreads();
    }
    #pragma unroll
    for (int r = 0; r < 8; ++r) {
        float4 o = make_float4(acc[r][0], acc[r][1], acc[r][2], acc[r][3]);
        *(float4*)(g_Wc + (size_t)(q0 + ty*8 + r)*NPAD + tx*4) = o;
    }
}

// ---------------- Kernel 6: logits partials = (zh (x) zt) . Wc -------------------------
// Grid: (NS/32 sample tiles, QSL q-slices).  Per thread: 4 samples x 4 classes.
__global__ void k_logits()
{
    int s0 = blockIdx.x * 32;
    int k0 = blockIdx.y * (KB/QSL);      // 3 k-blocks per slice
    int tid = threadIdx.x, tx = tid % 32, ty = tid / 32;
    __shared__ float zh_s[32][BLK];
    __shared__ float zt_s[32][BLK];
    __shared__ float A_s [32][BLK];
    float acc[4][4] = {};

    int ls = tid / 8, lj0 = (tid % 8) * 8;   // cooperative load/build map

    for (int kq = 0; kq < KB/QSL; ++kq) {
        int k = k0 + kq;
        const float* ph = g_zh + (size_t)(s0+ls)*HH + k*BLK + lj0;
        const float* pt = g_zt + (size_t)(s0+ls)*HH + k*BLK + lj0;
        *(float4*)&zh_s[ls][lj0]   = *(const float4*)(ph);
        *(float4*)&zh_s[ls][lj0+4] = *(const float4*)(ph+4);
        *(float4*)&zt_s[ls][lj0]   = *(const float4*)(pt);
        *(float4*)&zt_s[ls][lj0+4] = *(const float4*)(pt+4);
        __syncthreads();

        for (int i = 0; i < BLK; ++i) {
            // build A_s[s][j] = zh[s][i] * zt[s][j]
            {
                float zi = zh_s[ls][i];
                float4 t0 = *(float4*)&zt_s[ls][lj0];
                float4 t1 = *(float4*)&zt_s[ls][lj0+4];
                *(float4*)&A_s[ls][lj0]   = make_float4(zi*t0.x, zi*t0.y, zi*t0.z, zi*t0.w);
                *(float4*)&A_s[ls][lj0+4] = make_float4(zi*t1.x, zi*t1.y, zi*t1.z, zi*t1.w);
            }
            __syncthreads();

            const float* wrow = g_Wc + (size_t)((k*BLK + i)*BLK)*NPAD + tx*4;
            #pragma unroll 4
            for (int j = 0; j < BLK; ++j) {
                float4 w = *(const float4*)(wrow + (size_t)j*NPAD);
                #pragma unroll
                for (int g = 0; g < 4; ++g) {
                    float a = A_s[ty + 8*g][j];
                    acc[g][0] += a*w.x; acc[g][1] += a*w.y;
                    acc[g][2] += a*w.z; acc[g][3] += a*w.w;
                }
            }
            __syncthreads();
        }
    }
    float* pp = g_part + (size_t)blockIdx.y*NS*NCLS;
    #pragma unroll
    for (int g = 0; g < 4; ++g) {
        int s = s0 + ty + 8*g;
        #pragma unroll
        for (int c = 0; c < 4; ++c) {
            int n = tx*4 + c;
            if (n < NCLS) pp[(size_t)s*NCLS + n] = acc[g][c];
        }
    }
}

// ---------------- Kernel 7: reduce q-slice partials + bias -----------------------------
__global__ void k_reduce(const float* __restrict__ bcls, float* __restrict__ out)
{
    int idx = blockIdx.x*256 + threadIdx.x;
    if (idx >= NS*NCLS) return;
    int n = idx % NCLS;
    float v = bcls[n];
    #pragma unroll
    for (int sl = 0; sl < QSL; ++sl) v += g_part[(size_t)sl*NS*NCLS + idx];
    out[idx] = v;
}

// ---------------- launch --------------------------------------------------------------
extern "C" void kernel_launch(void* const* d_in, const int* in_sizes, int n_in,
                              void* d_out, int out_size)
{
    (void)in_sizes; (void)n_in; (void)out_size;
    const float* seq   = (const float*)d_in[0];
    const float* att   = (const float*)d_in[1];
    const int*   mst   = (const int*)  d_in[2];
    const int*   cst   = (const int*)  d_in[3];
    const float* Wh    = (const float*)d_in[4];
    const float* bh    = (const float*)d_in[5];
    const float* Wt    = (const float*)d_in[6];
    const float* bt    = (const float*)d_in[7];
    const float* Wproj = (const float*)d_in[8];
    const float* Wcls  = (const float*)d_in[9];
    const float* bcls  = (const float*)d_in[10];
    float* out = (float*)d_out;

    k_entity<<<BB*NE, 256>>>(seq, att, mst, cst);
    k_ht<<<BB*NE*NE, 256>>>();
    {
        dim3 g(NE*NE/64, HH/64, BB);            // 9 x 12 x 2
        k_rs<<<g, 256>>>(seq);
    }
    {
        dim3 g(BB*NE, 2);
        k_AhAt<<<g, 256>>>(Wh, bh, Wt, bt);
    }
    {
        dim3 g(NS/64, (2*HH)/64);               // 18 x 24
        k_zhzt<<<g, 256>>>(Wh, Wt);
    }
    k_wclsT<<<(HH*NPAD)/256, 256>>>(Wcls);
    k_wc<<<QTOT/64, 256>>>(Wproj);              // 768 CTAs
    {
        dim3 g(NS/32, QSL);                     // 36 x 4 = 144 CTAs
        k_logits<<<g, 256>>>();
    }
    k_reduce<<<(NS*NCLS + 255)/256, 256>>>(bcls, out);
}

// round 8
// speedup vs baseline: 2.6351x; 2.6351x over previous
#include <cuda_runtime.h>
#include <math.h>
#include <stdint.h>

// Problem constants
#define BB     2
#define LL     1024
#define HH     768
#define NHEADS 12
#define NE     24
#define MM     3
#define NC     2
#define CWW    8
#define BLK    64
#define NCLS   97
#define KB     12              // H / BLOCK
#define QTOT   (HH*BLK)        // 49152
#define NS     (BB*NE*NE)      // 1152
#define NPAD   128
#define KSL    12              // k-slices in logits kernel (one 64x64 block each)

// ---------------- device scratch (no runtime allocation allowed) ----------------
__device__ float g_eatt[BB*NE*NHEADS*LL];       // (b,e,h,l)  mean over mentions
__device__ float g_eemb[BB*NE*HH];              // logsumexp entity embedding
__device__ float g_ht[BB*NE*NE*LL];             // normalized relu attention product
__device__ float g_rs[(size_t)NS*HH];           // context vectors
__device__ float g_Ah[BB*NE*HH];                // e_emb @ Wh1^T + b_head
__device__ float g_At[BB*NE*HH];                // e_emb @ Wt1^T + b_tail
__device__ float g_zh[(size_t)NS*HH];
__device__ float g_zt[(size_t)NS*HH];
__device__ float g_WclsT[HH*NPAD];              // W_cls transposed, n-padded to 128
__device__ float g_Wc[(size_t)QTOT*NPAD];       // folded W_cls @ W_proj, layout [q][n]
__device__ float g_part[(size_t)KSL*NS*NCLS];   // logits partial sums per k-slice

// ---------------- Kernel 1: entity gather / gate / coref / logsumexp ----------------
__global__ void k_entity(const float* __restrict__ seq, const float* __restrict__ att,
                         const int* __restrict__ mst, const int* __restrict__ cst)
{
    int be  = blockIdx.x;           // b*NE + e
    int b   = be / NE;
    int tid = threadIdx.x;

    __shared__ float s_att[LL];
    __shared__ float s_gate[NC*CWW];
    __shared__ float s_red[256];
    __shared__ int   s_p[MM];
    __shared__ int   s_c[NC];

    if (tid < MM) s_p[tid] = mst[be*MM + tid] + 1;      // OFFSET = 1
    if (tid >= 32 && tid < 32+NC) s_c[tid-32] = cst[be*NC + (tid-32)];
    __syncthreads();

    int p0 = s_p[0], p1 = s_p[1], p2 = s_p[2];
    const float* ab = att + (size_t)b*NHEADS*LL*LL;

    for (int h = 0; h < NHEADS; ++h) {
        const float* r0 = ab + ((size_t)h*LL + p0)*LL;
        const float* r1 = ab + ((size_t)h*LL + p1)*LL;
        const float* r2 = ab + ((size_t)h*LL + p2)*LL;
        float* eo = g_eatt + ((size_t)be*NHEADS + h)*LL;
        for (int l = tid; l < LL; l += 256) {
            float v = (r0[l] + r1[l] + r2[l]) * (1.0f/3.0f);
            eo[l] = v;
            if (h == 0) s_att[l] = v; else s_att[l] += v;
        }
    }
    __syncthreads();

    float lsum = 0.f;
    for (int l = tid; l < LL; l += 256) lsum += s_att[l];
    s_red[tid] = lsum;
    __syncthreads();
    for (int off = 128; off > 0; off >>= 1) {
        if (tid < off) s_red[tid] += s_red[tid+off];
        __syncthreads();
    }
    float inv = 1.0f / s_red[0];

    if (tid < NC*CWW) {
        int c = tid / CWW, w = tid % CWW;
        s_gate[tid] = s_att[s_c[c] + w] * inv;
    }
    __syncthreads();

    const float* sb = seq + (size_t)b*LL*HH;
    int c0 = s_c[0], c1 = s_c[1];
    for (int d = tid; d < HH; d += 256) {
        float v0 = sb[(size_t)p0*HH + d];
        float v1 = sb[(size_t)p1*HH + d];
        float v2 = sb[(size_t)p2*HH + d];
        float v3 = 0.f, v4 = 0.f;
        #pragma unroll
        for (int w = 0; w < CWW; ++w) {
            v3 += s_gate[w]       * sb[(size_t)(c0+w)*HH + d];
            v4 += s_gate[CWW+w]   * sb[(size_t)(c1+w)*HH + d];
        }
        float mx = fmaxf(fmaxf(fmaxf(v0,v1), fmaxf(v2,v3)), v4);
        float s  = expf(v0-mx)+expf(v1-mx)+expf(v2-mx)+expf(v3-mx)+expf(v4-mx);
        g_eemb[(size_t)be*HH + d] = mx + logf(s);
    }
}

// ---------------- Kernel 2: ht = norm(relu(e_att . e_att^T over heads)) ----------------
__global__ void k_ht()
{
    int bef = blockIdx.x;                   // b*NE*NE + e*NE + f
    int b = bef / (NE*NE);
    int ef = bef % (NE*NE);
    int e = ef / NE, f = ef % NE;
    const float* pe = g_eatt + (size_t)(b*NE+e)*NHEADS*LL;
    const float* pf = g_eatt + (size_t)(b*NE+f)*NHEADS*LL;
    int tid = threadIdx.x;
    __shared__ float s_red[256];

    float v[4];
    float lsum = 0.f;
    #pragma unroll
    for (int r = 0; r < 4; ++r) {
        int l = r*256 + tid;
        float acc = 0.f;
        #pragma unroll
        for (int h = 0; h < NHEADS; ++h)
            acc += pe[h*LL + l] * pf[h*LL + l];
        v[r] = fmaxf(acc, 0.f);
        lsum += v[r];
    }
    s_red[tid] = lsum;
    __syncthreads();
    for (int off = 128; off > 0; off >>= 1) {
        if (tid < off) s_red[tid] += s_red[tid+off];
        __syncthreads();
    }
    float invn = 1.0f / (s_red[0] + 1e-10f);
    float* out = g_ht + (size_t)bef*LL;
    #pragma unroll
    for (int r = 0; r < 4; ++r) out[r*256 + tid] = v[r] * invn;
}

// ---------------- Kernel 3: rs[b] = ht[b] (576x1024) @ seq[b] (1024x768) ----------------
__global__ void k_rs(const float* __restrict__ seq)
{
    const int BM=64, BN=64, BK=16;
    int bm = blockIdx.x, bn = blockIdx.y, b = blockIdx.z;
    const float* A  = g_ht + (size_t)b*NE*NE*LL;
    const float* Bm = seq  + (size_t)b*LL*HH;
    __shared__ float As[BK][BM];
    __shared__ float Bs[BK][BN];
    int tid = threadIdx.x;
    int tx = tid % 16, ty = tid / 16;
    int arow = tid / 4,  acol4 = (tid % 4) * 4;
    int brow = tid / 16, bcol4 = (tid % 16) * 4;
    float acc[4][4] = {};

    for (int k0 = 0; k0 < LL; k0 += BK) {
        float4 a4 = *(const float4*)(A  + (size_t)(bm*BM + arow)*LL + k0 + acol4);
        float4 b4 = *(const float4*)(Bm + (size_t)(k0 + brow)*HH + bn*BN + bcol4);
        As[acol4+0][arow] = a4.x; As[acol4+1][arow] = a4.y;
        As[acol4+2][arow] = a4.z; As[acol4+3][arow] = a4.w;
        *(float4*)&Bs[brow][bcol4] = b4;
        __syncthreads();
        #pragma unroll
        for (int kk = 0; kk < BK; ++kk) {
            float4 av = *(float4*)&As[kk][ty*4];
            float4 bv = *(float4*)&Bs[kk][tx*4];
            acc[0][0]+=av.x*bv.x; acc[0][1]+=av.x*bv.y; acc[0][2]+=av.x*bv.z; acc[0][3]+=av.x*bv.w;
            acc[1][0]+=av.y*bv.x; acc[1][1]+=av.y*bv.y; acc[1][2]+=av.y*bv.z; acc[1][3]+=av.y*bv.w;
            acc[2][0]+=av.z*bv.x; acc[2][1]+=av.z*bv.y; acc[2][2]+=av.z*bv.z; acc[2][3]+=av.z*bv.w;
            acc[3][0]+=av.w*bv.x; acc[3][1]+=av.w*bv.y; acc[3][2]+=av.w*bv.z; acc[3][3]+=av.w*bv.w;
        }
        __syncthreads();
    }
    #pragma unroll
    for (int i = 0; i < 4; ++i) {
        float4 o = make_float4(acc[i][0], acc[i][1], acc[i][2], acc[i][3]);
        *(float4*)(g_rs + (size_t)(b*NE*NE + bm*BM + ty*4 + i)*HH + bn*BN + tx*4) = o;
    }
}

// ---------------- Kernel 4a: Ah/At = e_emb @ W1^T + bias (tiled GEMM) ------------------
// Grid (HH/64, 2). Block 256. Out tile 48 rows (all entities) x 64 cols (d).
__global__ void k_AhAt(const float* __restrict__ Wh, const float* __restrict__ bh,
                       const float* __restrict__ Wt, const float* __restrict__ bt)
{
    const int BN = 64, BK = 16;
    int d0    = blockIdx.x * BN;
    int which = blockIdx.y;
    const float* W    = which ? Wt : Wh;
    const float* bias = which ? bt : bh;
    float* Out        = which ? g_At : g_Ah;

    __shared__ float e_s[BK][48+2];     // transposed: e_s[k][be]
    __shared__ float W_s[BK][BN+4];     // transposed: W_s[k][d]

    int tid = threadIdx.x;
    int tx = tid % 16, ty = tid / 16;   // tx -> 4 d's, ty -> 3 entities
    float acc[3][4] = {};

    int er = tid / 4,  ec4 = (tid % 4) * 4;   // e load map (rows 0..47 need tid<192)
    int wr = tid / 4,  wc4 = (tid % 4) * 4;   // W load map (rows 0..63)

    for (int k0 = 0; k0 < HH; k0 += BK) {
        if (tid < 192) {
            float4 a4 = *(const float4*)(g_eemb + (size_t)er*HH + k0 + ec4);
            e_s[ec4+0][er]=a4.x; e_s[ec4+1][er]=a4.y; e_s[ec4+2][er]=a4.z; e_s[ec4+3][er]=a4.w;
        }
        {
            float4 w4 = *(const float4*)(W + (size_t)(d0+wr)*(2*HH) + k0 + wc4);
            W_s[wc4+0][wr]=w4.x; W_s[wc4+1][wr]=w4.y; W_s[wc4+2][wr]=w4.z; W_s[wc4+3][wr]=w4.w;
        }
        __syncthreads();
        #pragma unroll
        for (int kk = 0; kk < BK; ++kk) {
            float4 wv = *(float4*)&W_s[kk][tx*4];
            #pragma unroll
            for (int si = 0; si < 3; ++si) {
                float a = e_s[kk][ty*3 + si];
                acc[si][0]+=a*wv.x; acc[si][1]+=a*wv.y; acc[si][2]+=a*wv.z; acc[si][3]+=a*wv.w;
            }
        }
        __syncthreads();
    }
    #pragma unroll
    for (int si = 0; si < 3; ++si) {
        int be = ty*3 + si;
        #pragma unroll
        for (int c = 0; c < 4; ++c) {
            int d = d0 + tx*4 + c;
            Out[(size_t)be*HH + d] = acc[si][c] + bias[d];
        }
    }
}

// ---------------- Kernel 4b: [zh|zt] = tanh(rs @ W2^T + A) -----------------------------
__global__ void k_zhzt(const float* __restrict__ Wh, const float* __restrict__ Wt)
{
    const int BM=64, BN=64, BK=16;
    int bm = blockIdx.x, bn = blockIdx.y;
    bool isHead = (bn < HH/BN);
    const float* W = isHead ? Wh : Wt;
    int ncol0 = (isHead ? bn : bn - HH/BN) * BN;

    __shared__ float As[BK][BM];
    __shared__ float Bs[BK][BN];
    int tid = threadIdx.x;
    int tx = tid % 16, ty = tid / 16;
    int arow = tid / 4, acol4 = (tid % 4) * 4;
    float acc[4][4] = {};

    for (int k0 = 0; k0 < HH; k0 += BK) {
        float4 a4 = *(const float4*)(g_rs + (size_t)(bm*BM + arow)*HH + k0 + acol4);
        float4 b4 = *(const float4*)(W + (size_t)(ncol0 + arow)*(2*HH) + HH + k0 + acol4);
        As[acol4+0][arow] = a4.x; As[acol4+1][arow] = a4.y;
        As[acol4+2][arow] = a4.z; As[acol4+3][arow] = a4.w;
        Bs[acol4+0][arow] = b4.x; Bs[acol4+1][arow] = b4.y;
        Bs[acol4+2][arow] = b4.z; Bs[acol4+3][arow] = b4.w;
        __syncthreads();
        #pragma unroll
        for (int kk = 0; kk < BK; ++kk) {
            float4 av = *(float4*)&As[kk][ty*4];
            float4 bv = *(float4*)&Bs[kk][tx*4];
            acc[0][0]+=av.x*bv.x; acc[0][1]+=av.x*bv.y; acc[0][2]+=av.x*bv.z; acc[0][3]+=av.x*bv.w;
            acc[1][0]+=av.y*bv.x; acc[1][1]+=av.y*bv.y; acc[1][2]+=av.y*bv.z; acc[1][3]+=av.y*bv.w;
            acc[2][0]+=av.z*bv.x; acc[2][1]+=av.z*bv.y; acc[2][2]+=av.z*bv.z; acc[2][3]+=av.z*bv.w;
            acc[3][0]+=av.w*bv.x; acc[3][1]+=av.w*bv.y; acc[3][2]+=av.w*bv.z; acc[3][3]+=av.w*bv.w;
        }
        __syncthreads();
    }
    float* Z = isHead ? g_zh : g_zt;
    #pragma unroll
    for (int i = 0; i < 4; ++i) {
        int s  = bm*BM + ty*4 + i;
        int b  = s / (NE*NE);
        int ef = s % (NE*NE);
        int e  = ef / NE, f = ef % NE;
        const float* Avec = isHead ? (g_Ah + (size_t)(b*NE+e)*HH)
                                   : (g_At + (size_t)(b*NE+f)*HH);
        #pragma unroll
        for (int j = 0; j < 4; ++j) {
            int col = ncol0 + tx*4 + j;
            Z[(size_t)s*HH + col] = tanhf(acc[i][j] + Avec[col]);
        }
    }
}

// ---------------- Kernel 5a: transpose W_cls -> [d][n] padded to 128 -------------------
__global__ void k_wclsT(const float* __restrict__ Wcls)
{
    int idx = blockIdx.x*256 + threadIdx.x;
    if (idx >= HH*NPAD) return;
    int d = idx / NPAD, n = idx % NPAD;
    g_WclsT[idx] = (n < NCLS) ? Wcls[(size_t)n*HH + d] : 0.f;
}

// ---------------- Kernel 5b: Wc[q][n] = sum_d W_proj[d][q] * W_cls[n][d] ---------------
__global__ void k_wc(const float* __restrict__ Wproj)
{
    const int QT = 64, DB = 16;
    int q0 = blockIdx.x * QT;
    int tid = threadIdx.x, tx = tid % 32, ty = tid / 32;
    __shared__ float Wp_s[DB][QT];
    __shared__ float Wt_s[DB][NPAD];
    float acc[8][4] = {};

    int pr = tid / 16, pc4 = (tid % 16) * 4;    // Wp tile load map
    int cr = tid / 32, cc4 = (tid % 32) * 4;    // WclsT tile load map

    for (int d0 = 0; d0 < HH; d0 += DB) {
        *(float4*)&Wp_s[pr][pc4]   = *(const float4*)(Wproj + (size_t)(d0+pr)*QTOT + q0 + pc4);
        *(float4*)&Wt_s[cr][cc4]   = *(const float4*)(g_WclsT + (size_t)(d0+cr)*NPAD + cc4);
        *(float4*)&Wt_s[cr+8][cc4] = *(const float4*)(g_WclsT + (size_t)(d0+cr+8)*NPAD + cc4);
        __syncthreads();
        #pragma unroll
        for (int dd = 0; dd < DB; ++dd) {
            float4 wq0 = *(float4*)&Wp_s[dd][ty*8];
            float4 wq1 = *(float4*)&Wp_s[dd][ty*8+4];
            float4 wn  = *(float4*)&Wt_s[dd][tx*4];
            float wq[8] = {wq0.x,wq0.y,wq0.z,wq0.w,wq1.x,wq1.y,wq1.z,wq1.w};
            #pragma unroll
            for (int r = 0; r < 8; ++r) {
                acc[r][0] += wq[r]*wn.x;
                acc[r][1] += wq[r]*wn.y;
                acc[r][2] += wq[r]*wn.z;
                acc[r][3] += wq[r]*wn.w;
            }
        }
        __syncthreads();
    }
    #pragma unroll
    for (int r = 0; r < 8; ++r) {
        float4 o = make_float4(acc[r][0], acc[r][1], acc[r][2], acc[r][3]);
        *(float4*)(g_Wc + (size_t)(q0 + ty*8 + r)*NPAD + tx*4) = o;
    }
}

// ---------------- Kernel 6: logits partials = (zh (x) zt) . Wc -------------------------
// Barrier-free mainloop: a = zh_i * zt_j generated on the fly.
// Grid (NS/32 sample tiles, KSL k-blocks). Block 256 = 32 tx (classes) x 8 ty.
// Per thread: 4 samples (ty + 8g) x 4 classes (tx*4..tx*4+3).
__global__ void k_logits()
{
    int s0 = blockIdx.x * 32;
    int k  = blockIdx.y;                 // one 64x64 (i,j) block per CTA
    int tid = threadIdx.x, tx = tid % 32, ty = tid / 32;

    __shared__ float zh_s[32][BLK];
    __shared__ float zt_s[32][BLK];
    float acc[4][4] = {};

    // cooperative tile load: 32 rows x 64 floats = 512 float4, 2 per thread
    {
        int r  = tid / 8;                // 0..31
        int c4 = (tid % 8) * 8;          // 0,8,...,56
        const float* ph = g_zh + (size_t)(s0+r)*HH + k*BLK + c4;
        const float* pt = g_zt + (size_t)(s0+r)*HH + k*BLK + c4;
        *(float4*)&zh_s[r][c4]   = *(const float4*)(ph);
        *(float4*)&zh_s[r][c4+4] = *(const float4*)(ph+4);
        *(float4*)&zt_s[r][c4]   = *(const float4*)(pt);
        *(float4*)&zt_s[r][c4+4] = *(const float4*)(pt+4);
    }
    __syncthreads();

    for (int i = 0; i < BLK; ++i) {
        float zh_i[4];
        #pragma unroll
        for (int g = 0; g < 4; ++g) zh_i[g] = zh_s[ty + 8*g][i];   // LDS broadcast

        const float* wrow = g_Wc + (size_t)((k*BLK + i)*BLK)*NPAD + tx*4;
        #pragma unroll 4
        for (int j = 0; j < BLK; ++j) {
            float4 w = *(const float4*)(wrow + (size_t)j*NPAD);    // coalesced LDG.128
            #pragma unroll
            for (int g = 0; g < 4; ++g) {
                float a = zh_i[g] * zt_s[ty + 8*g][j];
                acc[g][0] += a*w.x; acc[g][1] += a*w.y;
                acc[g][2] += a*w.z; acc[g][3] += a*w.w;
            }
        }
    }

    float* pp = g_part + (size_t)k*NS*NCLS;
    #pragma unroll
    for (int g = 0; g < 4; ++g) {
        int s = s0 + ty + 8*g;
        #pragma unroll
        for (int c = 0; c < 4; ++c) {
            int n = tx*4 + c;
            if (n < NCLS) pp[(size_t)s*NCLS + n] = acc[g][c];
        }
    }
}

// ---------------- Kernel 7: reduce k-slice partials + bias -----------------------------
__global__ void k_reduce(const float* __restrict__ bcls, float* __restrict__ out)
{
    int idx = blockIdx.x*256 + threadIdx.x;
    if (idx >= NS*NCLS) return;
    int n = idx % NCLS;
    float v = bcls[n];
    #pragma unroll
    for (int sl = 0; sl < KSL; ++sl) v += g_part[(size_t)sl*NS*NCLS + idx];
    out[idx] = v;
}

// ---------------- launch --------------------------------------------------------------
extern "C" void kernel_launch(void* const* d_in, const int* in_sizes, int n_in,
                              void* d_out, int out_size)
{
    (void)in_sizes; (void)n_in; (void)out_size;
    const float* seq   = (const float*)d_in[0];
    const float* att   = (const float*)d_in[1];
    const int*   mst   = (const int*)  d_in[2];
    const int*   cst   = (const int*)  d_in[3];
    const float* Wh    = (const float*)d_in[4];
    const float* bh    = (const float*)d_in[5];
    const float* Wt    = (const float*)d_in[6];
    const float* bt    = (const float*)d_in[7];
    const float* Wproj = (const float*)d_in[8];
    const float* Wcls  = (const float*)d_in[9];
    const float* bcls  = (const float*)d_in[10];
    float* out = (float*)d_out;

    k_entity<<<BB*NE, 256>>>(seq, att, mst, cst);
    k_ht<<<BB*NE*NE, 256>>>();
    {
        dim3 g(NE*NE/64, HH/64, BB);            // 9 x 12 x 2
        k_rs<<<g, 256>>>(seq);
    }
    {
        dim3 g(HH/64, 2);                       // 12 x 2
        k_AhAt<<<g, 256>>>(Wh, bh, Wt, bt);
    }
    {
        dim3 g(NS/64, (2*HH)/64);               // 18 x 24
        k_zhzt<<<g, 256>>>(Wh, Wt);
    }
    k_wclsT<<<(HH*NPAD)/256, 256>>>(Wcls);
    k_wc<<<QTOT/64, 256>>>(Wproj);              // 768 CTAs
    {
        dim3 g(NS/32, KSL);                     // 36 x 12 = 432 CTAs
        k_logits<<<g, 256>>>();
    }
    k_reduce<<<(NS*NCLS + 255)/256, 256>>>(bcls, out);
}